// round 9
// baseline (speedup 1.0000x reference)
#include <cuda_runtime.h>
#include <cuda_bf16.h>
#include <cstdint>

// ---------------- problem constants ----------------
#define N_TOT 8192
#define D     128
#define IPC_C 512
#define ROW0  7680            // bz - IPC
#define NCOL  7680            // unmasked columns [0, 7680)
#define BM    128
#define BN    128
#define NTIL  (NCOL / BN)     // 60 column tiles
#define ETIL  (1024 / BN)     // tiles [0,8) = easy region (exact boundary)
#define NBLK  (NTIL * (IPC_C / BM))   // 240 blocks, 2 per SM
#define LDB   136             // bf16 smem row stride; 68 uint32

// ---------------- device globals ----------------
__device__ __nv_bfloat16 g_bf[N_TOT * D];   // normalized bf16
__device__ float g_part[NTIL * IPC_C];      // [colTile][row]
__device__ int   g_done;                    // zero-init; reset each replay

#define CP_ASYNC16(dst_u32, src_ptr) \
    asm volatile("cp.async.cg.shared.global [%0], [%1], 16;" \
                 :: "r"(dst_u32), "l"(src_ptr) : "memory")
#define CP_COMMIT()  asm volatile("cp.async.commit_group;" ::: "memory")
#define CP_WAIT0()   asm volatile("cp.async.wait_group 0;" ::: "memory")

// ---------------- kernel 1: normalize -> bf16 (8 threads per row) ----------------
__global__ void __launch_bounds__(256) prep_kernel(const float* __restrict__ f) {
    const int t    = threadIdx.x;
    const int row  = blockIdx.x * 32 + (t >> 3);
    const int l8   = t & 7;
    const float4* src = (const float4*)(f + (size_t)row * D);

    float4 v[4];
    float s = 0.f;
    #pragma unroll
    for (int j = 0; j < 4; j++) {
        v[j] = src[l8 + 8 * j];
        s += v[j].x * v[j].x + v[j].y * v[j].y + v[j].z * v[j].z + v[j].w * v[j].w;
    }
    #pragma unroll
    for (int o = 1; o < 8; o <<= 1) s += __shfl_xor_sync(0xffffffffu, s, o);
    float inv = rsqrtf(s);
    if (!(s > 1e-24f)) inv = 1e12f;

    #pragma unroll
    for (int j = 0; j < 4; j++) {
        __nv_bfloat162 p0 = __floats2bfloat162_rn(v[j].x * inv, v[j].y * inv);
        __nv_bfloat162 p1 = __floats2bfloat162_rn(v[j].z * inv, v[j].w * inv);
        uint2 packed = make_uint2(*(uint32_t*)&p0, *(uint32_t*)&p1);
        *(uint2*)(g_bf + (size_t)row * D + l8 * 4 + 32 * j) = packed;
    }
}

// ---------------- kernel 2: bf16 m16n8k16 GEMM (128x128 tile) ----------------
// 512 threads = 16 warps (4m x 4n); warp tile 32x32. 2 blocks per SM.
// smem: A bf16[128][136] + B bf16[128][136] = 69632 B
#define SMEM_BYTES (BM * LDB * 2 + BN * LDB * 2)

__global__ void __launch_bounds__(512, 2) gemm_kernel(const float* __restrict__ a_scl,
                                                      float* __restrict__ out) {
    extern __shared__ char smraw[];
    __nv_bfloat16* As = (__nv_bfloat16*)smraw;
    __nv_bfloat16* Bs = As + BM * LDB;

    const int tid  = threadIdx.x;
    const int lane = tid & 31;
    const int w    = tid >> 5;
    const int wm   = w >> 2;        // 0..3 -> 32-row strip
    const int wn   = w & 3;         // 0..3 -> 32-col strip
    const int q    = lane >> 2;     // 0..7
    const int tig  = lane & 3;      // 0..3
    const int rowBase = ROW0 + blockIdx.y * BM;
    const int colBase = blockIdx.x * BN;

    const uint32_t sA = (uint32_t)__cvta_generic_to_shared(As);
    const uint32_t sB = (uint32_t)__cvta_generic_to_shared(Bs);

    // ---- stage A and B: 128 rows x 16 chunks of 16B each ----
    #pragma unroll
    for (int t = 0; t < 4; t++) {
        int idx = tid + t * 512;
        int r = idx >> 4, c = idx & 15;
        CP_ASYNC16(sA + r * (LDB * 2) + c * 16,
                   g_bf + (size_t)(rowBase + r) * D + c * 8);
    }
    #pragma unroll
    for (int t = 0; t < 4; t++) {
        int idx = tid + t * 512;
        int r = idx >> 4, c = idx & 15;
        CP_ASYNC16(sB + r * (LDB * 2) + c * 16,
                   g_bf + (size_t)(colBase + r) * D + c * 8);
    }
    CP_COMMIT();
    CP_WAIT0();
    __syncthreads();

    float acc[2][4][4];
    #pragma unroll
    for (int mt = 0; mt < 2; mt++)
        #pragma unroll
        for (int nt = 0; nt < 4; nt++)
            #pragma unroll
            for (int e = 0; e < 4; e++) acc[mt][nt][e] = 0.f;

    const uint32_t* A32 = (const uint32_t*)As;   // row*68 + kpair
    const uint32_t* B32 = (const uint32_t*)Bs;
    const int rA0 = wm * 32 + q;
    const int rB0 = wn * 32 + q;

    #pragma unroll
    for (int s = 0; s < 8; s++) {            // 8 K-steps of k16
        const int ko = s * 8 + tig;
        uint32_t af[2][4];
        #pragma unroll
        for (int mt = 0; mt < 2; mt++) {
            int b0 = (rA0 + mt * 16) * 68 + ko;
            af[mt][0] = A32[b0];
            af[mt][1] = A32[b0 + 8 * 68];
            af[mt][2] = A32[b0 + 4];
            af[mt][3] = A32[b0 + 8 * 68 + 4];
        }
        uint32_t bf[4][2];
        #pragma unroll
        for (int nt = 0; nt < 4; nt++) {
            int b0 = (rB0 + nt * 8) * 68 + ko;
            bf[nt][0] = B32[b0];
            bf[nt][1] = B32[b0 + 4];
        }
        #pragma unroll
        for (int mt = 0; mt < 2; mt++)
            #pragma unroll
            for (int nt = 0; nt < 4; nt++)
                asm volatile(
                    "mma.sync.aligned.m16n8k16.row.col.f32.bf16.bf16.f32 "
                    "{%0,%1,%2,%3}, {%4,%5,%6,%7}, {%8,%9}, {%0,%1,%2,%3};"
                    : "+f"(acc[mt][nt][0]), "+f"(acc[mt][nt][1]),
                      "+f"(acc[mt][nt][2]), "+f"(acc[mt][nt][3])
                    : "r"(af[mt][0]), "r"(af[mt][1]), "r"(af[mt][2]), "r"(af[mt][3]),
                      "r"(bf[nt][0]), "r"(bf[nt][1]));
    }
    __syncthreads();   // all smem reads done before reuse

    // ---- row max: thread -> quad shfl -> cross-warp via smem ----
    float* pm = (float*)smraw;    // [4(wn)][128]
    #pragma unroll
    for (int mt = 0; mt < 2; mt++) {
        float mlo = -2.f, mhi = -2.f;
        #pragma unroll
        for (int nt = 0; nt < 4; nt++) {
            mlo = fmaxf(mlo, fmaxf(acc[mt][nt][0], acc[mt][nt][1]));
            mhi = fmaxf(mhi, fmaxf(acc[mt][nt][2], acc[mt][nt][3]));
        }
        #pragma unroll
        for (int o = 1; o < 4; o <<= 1) {
            mlo = fmaxf(mlo, __shfl_xor_sync(0xffffffffu, mlo, o));
            mhi = fmaxf(mhi, __shfl_xor_sync(0xffffffffu, mhi, o));
        }
        if (tig == 0) {
            int r = wm * 32 + mt * 16 + q;
            pm[wn * 128 + r]     = mlo;
            pm[wn * 128 + r + 8] = mhi;
        }
    }
    __syncthreads();

    if (tid < BM) {
        float m = fmaxf(fmaxf(pm[tid], pm[128 + tid]),
                        fmaxf(pm[256 + tid], pm[384 + tid]));
        g_part[blockIdx.x * IPC_C + blockIdx.y * BM + tid] = m;
    }
    __syncthreads();

    // ---- last-block-done fused finalize ----
    __shared__ int isLast;
    __shared__ float red[512];
    if (tid == 0) {
        __threadfence();
        isLast = (atomicAdd(&g_done, 1) == NBLK - 1);
    }
    __syncthreads();
    if (!isLast) return;
    if (tid == 0) __threadfence();
    __syncthreads();

    float e = -2.f, h = -2.f;
    #pragma unroll
    for (int j = 0; j < ETIL; j++)     e = fmaxf(e, g_part[j * IPC_C + tid]);
    #pragma unroll
    for (int j = ETIL; j < NTIL; j++)  h = fmaxf(h, g_part[j * IPC_C + tid]);
    red[tid] = log1pf(expf((h - e) * 10.0f));   // 1/SIGMA1 = 10
    __syncthreads();
    #pragma unroll
    for (int s2 = 256; s2; s2 >>= 1) {
        if (tid < s2) red[tid] += red[tid + s2];
        __syncthreads();
    }
    if (tid == 0) {
        out[0] = a_scl[0] * red[0] * (1.0f / 512.0f);
        g_done = 0;      // reset for the next graph replay
    }
}

extern "C" void kernel_launch(void* const* d_in, const int* in_sizes, int n_in,
                              void* d_out, int out_size) {
    const float* fvec = (const float*)d_in[0];   // [8192,128] f32
    // d_in[1] = Lvec (dead in the reference math)
    const float* a    = (const float*)d_in[2];   // scalar f32
    float* out = (float*)d_out;

    cudaFuncSetAttribute(gemm_kernel,
                         cudaFuncAttributeMaxDynamicSharedMemorySize, SMEM_BYTES);

    prep_kernel<<<N_TOT / 32, 256>>>(fvec);
    gemm_kernel<<<dim3(NTIL, IPC_C / BM), 512, SMEM_BYTES>>>(a, out);
}

// round 10
// speedup vs baseline: 1.0194x; 1.0194x over previous
#include <cuda_runtime.h>
#include <cuda_bf16.h>
#include <cstdint>

// ---------------- problem constants ----------------
#define N_TOT 8192
#define D     128
#define IPC_C 512
#define ROW0  7680            // bz - IPC
#define NCOL  7680            // unmasked columns [0, 7680)
#define BM    128
#define BN    256
#define NTIL  (NCOL / BN)     // 30 column tiles
#define ETIL  (1024 / BN)     // tiles [0,4) = easy region (exact boundary)
#define NBLK  (NTIL * (IPC_C / BM))   // 120 blocks = one wave
#define LDB   136             // bf16 smem row stride (bf16 units); 68 uint32

// ---------------- device globals ----------------
__device__ __nv_bfloat16 g_bf[N_TOT * D];   // normalized bf16
__device__ float g_part[NTIL * IPC_C];      // [colTile][row] partial maxima
__device__ int   g_done;                    // zero-init; reset each replay

#define CP_ASYNC16(dst_u32, src_ptr) \
    asm volatile("cp.async.cg.shared.global [%0], [%1], 16;" \
                 :: "r"(dst_u32), "l"(src_ptr) : "memory")
#define CP_COMMIT()  asm volatile("cp.async.commit_group;" ::: "memory")
#define CP_WAIT(n)   asm volatile("cp.async.wait_group %0;" :: "n"(n) : "memory")

// ---------------- kernel 1: normalize -> bf16 (8 threads per row) ----------------
__global__ void __launch_bounds__(256) prep_kernel(const float* __restrict__ f) {
    const int t   = threadIdx.x;
    const int row = blockIdx.x * 32 + (t >> 3);
    const int l8  = t & 7;
    const float4* src = (const float4*)(f + (size_t)row * D);

    float4 v[4];
    float s = 0.f;
    #pragma unroll
    for (int j = 0; j < 4; j++) {
        v[j] = src[l8 + 8 * j];
        s += v[j].x * v[j].x + v[j].y * v[j].y + v[j].z * v[j].z + v[j].w * v[j].w;
    }
    #pragma unroll
    for (int o = 1; o < 8; o <<= 1) s += __shfl_xor_sync(0xffffffffu, s, o);
    float inv = rsqrtf(s);
    if (!(s > 1e-24f)) inv = 1e12f;

    #pragma unroll
    for (int j = 0; j < 4; j++) {
        __nv_bfloat162 p0 = __floats2bfloat162_rn(v[j].x * inv, v[j].y * inv);
        __nv_bfloat162 p1 = __floats2bfloat162_rn(v[j].z * inv, v[j].w * inv);
        uint2 packed = make_uint2(*(uint32_t*)&p0, *(uint32_t*)&p1);
        *(uint2*)(g_bf + (size_t)row * D + l8 * 4 + 32 * j) = packed;
    }
}

// ---------------- kernel 2: bf16 m16n8k16 GEMM + row-max + fused finalize ----------------
// 512 threads = 16 warps (4m x 4n); warp tile 32x64; 120 blocks, one wave.
// smem: A bf16[128][136] + B bf16[256][136] = 104448 B
#define SMEM_BYTES (BM * LDB * 2 + BN * LDB * 2)

__global__ void __launch_bounds__(512, 1) gemm_kernel(const float* __restrict__ a_scl,
                                                      float* __restrict__ out) {
    extern __shared__ char smraw[];
    __nv_bfloat16* As = (__nv_bfloat16*)smraw;
    __nv_bfloat16* Bs = As + BM * LDB;

    const int tid  = threadIdx.x;
    const int lane = tid & 31;
    const int w    = tid >> 5;
    const int wm   = w >> 2;        // 0..3 -> 32-row strip
    const int wn   = w & 3;         // 0..3 -> 64-col strip
    const int q    = lane >> 2;     // 0..7
    const int tig  = lane & 3;      // 0..3
    const int rowBase = ROW0 + blockIdx.y * BM;
    const int colBase = blockIdx.x * BN;

    const uint32_t sA = (uint32_t)__cvta_generic_to_shared(As);
    const uint32_t sB = (uint32_t)__cvta_generic_to_shared(Bs);

    // ---- stage group 0: all of A + B k-half 0 (chunks 0..7) ----
    #pragma unroll
    for (int t = 0; t < 4; t++) {                  // A: 2048 16B chunks
        int idx = tid + t * 512;
        int r = idx >> 4, c = idx & 15;
        CP_ASYNC16(sA + r * (LDB * 2) + c * 16,
                   g_bf + (size_t)(rowBase + r) * D + c * 8);
    }
    #pragma unroll
    for (int t = 0; t < 4; t++) {                  // B half 0: 2048 chunks
        int idx = tid + t * 512;
        int r = idx >> 3, c = idx & 7;
        CP_ASYNC16(sB + r * (LDB * 2) + c * 16,
                   g_bf + (size_t)(colBase + r) * D + c * 8);
    }
    CP_COMMIT();
    // ---- stage group 1: B k-half 1 (chunks 8..15) ----
    #pragma unroll
    for (int t = 0; t < 4; t++) {
        int idx = tid + t * 512;
        int r = idx >> 3, c = (idx & 7) + 8;
        CP_ASYNC16(sB + r * (LDB * 2) + c * 16,
                   g_bf + (size_t)(colBase + r) * D + c * 8);
    }
    CP_COMMIT();

    float acc[2][8][4];
    #pragma unroll
    for (int mt = 0; mt < 2; mt++)
        #pragma unroll
        for (int nt = 0; nt < 8; nt++)
            #pragma unroll
            for (int e = 0; e < 4; e++) acc[mt][nt][e] = 0.f;

    const uint32_t* A32 = (const uint32_t*)As;   // row*68 + kpair
    const uint32_t* B32 = (const uint32_t*)Bs;
    const int rA0 = wm * 32 + q;
    const int rB0 = wn * 64 + q;

    CP_WAIT(1);           // group 0 resident (A + B k<64)
    __syncthreads();

    #pragma unroll
    for (int half = 0; half < 2; half++) {
        #pragma unroll
        for (int si = 0; si < 4; si++) {             // 4 K-steps of k16 per half
            const int ko = (half * 4 + si) * 8 + tig;
            uint32_t af[2][4];
            #pragma unroll
            for (int mt = 0; mt < 2; mt++) {
                int b0 = (rA0 + mt * 16) * 68 + ko;
                af[mt][0] = A32[b0];
                af[mt][1] = A32[b0 + 8 * 68];
                af[mt][2] = A32[b0 + 4];
                af[mt][3] = A32[b0 + 8 * 68 + 4];
            }
            uint32_t bf[8][2];
            #pragma unroll
            for (int nt = 0; nt < 8; nt++) {
                int b0 = (rB0 + nt * 8) * 68 + ko;
                bf[nt][0] = B32[b0];
                bf[nt][1] = B32[b0 + 4];
            }
            #pragma unroll
            for (int mt = 0; mt < 2; mt++)
                #pragma unroll
                for (int nt = 0; nt < 8; nt++)
                    asm volatile(
                        "mma.sync.aligned.m16n8k16.row.col.f32.bf16.bf16.f32 "
                        "{%0,%1,%2,%3}, {%4,%5,%6,%7}, {%8,%9}, {%0,%1,%2,%3};"
                        : "+f"(acc[mt][nt][0]), "+f"(acc[mt][nt][1]),
                          "+f"(acc[mt][nt][2]), "+f"(acc[mt][nt][3])
                        : "r"(af[mt][0]), "r"(af[mt][1]), "r"(af[mt][2]), "r"(af[mt][3]),
                          "r"(bf[nt][0]), "r"(bf[nt][1]));
        }
        if (half == 0) {
            CP_WAIT(0);   // B k-half 1 resident
            __syncthreads();
        }
    }
    __syncthreads();   // all smem reads done before reuse

    // ---- row max: thread -> quad shfl -> cross-warp via smem ----
    float* pm = (float*)smraw;    // [4(wn)][128]
    #pragma unroll
    for (int mt = 0; mt < 2; mt++) {
        float mlo = -2.f, mhi = -2.f;
        #pragma unroll
        for (int nt = 0; nt < 8; nt++) {
            mlo = fmaxf(mlo, fmaxf(acc[mt][nt][0], acc[mt][nt][1]));
            mhi = fmaxf(mhi, fmaxf(acc[mt][nt][2], acc[mt][nt][3]));
        }
        #pragma unroll
        for (int o = 1; o < 4; o <<= 1) {
            mlo = fmaxf(mlo, __shfl_xor_sync(0xffffffffu, mlo, o));
            mhi = fmaxf(mhi, __shfl_xor_sync(0xffffffffu, mhi, o));
        }
        if (tig == 0) {
            int r = wm * 32 + mt * 16 + q;
            pm[wn * 128 + r]     = mlo;
            pm[wn * 128 + r + 8] = mhi;
        }
    }
    __syncthreads();

    if (tid < BM) {
        float m = fmaxf(fmaxf(pm[tid], pm[128 + tid]),
                        fmaxf(pm[256 + tid], pm[384 + tid]));
        g_part[blockIdx.x * IPC_C + blockIdx.y * BM + tid] = m;
    }
    __syncthreads();

    // ---- last-block-done fused finalize (lean: shfl + smem atomics) ----
    __shared__ int isLast;
    __shared__ float sred;
    if (tid == 0) {
        __threadfence();
        isLast = (atomicAdd(&g_done, 1) == NBLK - 1);
    }
    __syncthreads();
    if (!isLast) return;

    if (tid == 0) { __threadfence(); sred = 0.f; }
    __syncthreads();

    float e = -2.f, h = -2.f;
    #pragma unroll
    for (int j = 0; j < ETIL; j++)     e = fmaxf(e, g_part[j * IPC_C + tid]);
    #pragma unroll
    for (int j = ETIL; j < NTIL; j++)  h = fmaxf(h, g_part[j * IPC_C + tid]);
    float loss = log1pf(expf((h - e) * 10.0f));   // 1/SIGMA1 = 10
    #pragma unroll
    for (int o = 16; o; o >>= 1) loss += __shfl_xor_sync(0xffffffffu, loss, o);
    if (lane == 0) atomicAdd(&sred, loss);
    __syncthreads();

    if (tid == 0) {
        out[0] = a_scl[0] * sred * (1.0f / 512.0f);
        g_done = 0;      // reset for the next graph replay
    }
}

extern "C" void kernel_launch(void* const* d_in, const int* in_sizes, int n_in,
                              void* d_out, int out_size) {
    const float* fvec = (const float*)d_in[0];   // [8192,128] f32
    // d_in[1] = Lvec (dead in the reference math)
    const float* a    = (const float*)d_in[2];   // scalar f32
    float* out = (float*)d_out;

    cudaFuncSetAttribute(gemm_kernel,
                         cudaFuncAttributeMaxDynamicSharedMemorySize, SMEM_BYTES);

    prep_kernel<<<N_TOT / 32, 256>>>(fvec);
    gemm_kernel<<<dim3(NTIL, IPC_C / BM), 512, SMEM_BYTES>>>(a, out);
}